// round 5
// baseline (speedup 1.0000x reference)
#include <cuda_runtime.h>
#include <cstdint>

#define NMAX 100000
#define EMAX 1600000
#define F1 512
#define F3 128
#define H 128
#define C 64
#define KTOT (F1 + F3)   // 640
#define SW 0.2f
#define FW 0.8f
#define BN_EPS 1e-5f

typedef unsigned long long ull;

// ---------------- device scratch (static, no allocations) ----------------
__device__ int   g_is64;
__device__ int   g_src[EMAX];
__device__ int   g_dst[EMAX];
__device__ int   g_deg[NMAX + 1];
__device__ int   g_off[NMAX + 1];
__device__ int   g_cur[NMAX];
__device__ int   g_bsum[128];
__device__ int   g_adj[EMAX];
__device__ float g_Wc[KTOT * H];      // fused [640,128] weight
__device__ float g_bz[H];
__device__ float g_scale[H];
__device__ float g_shift[H];
__device__ float g_z[(size_t)NMAX * H];     // 51.2 MB
__device__ float g_agg[(size_t)NMAX * H];   // 51.2 MB (post BN+ReLU)
__device__ float g_z2[(size_t)NMAX * C];    // 25.6 MB

// ---------------- packed f32x2 helpers ----------------
__device__ __forceinline__ ull pack2(float x) {
    ull r;
    asm("mov.b64 %0, {%1, %1};" : "=l"(r) : "r"(__float_as_uint(x)));
    return r;
}
__device__ __forceinline__ void ffma2(ull& d, ull a, ull b) {
    asm("fma.rn.f32x2 %0, %1, %2, %0;" : "+l"(d) : "l"(a), "l"(b));
}
__device__ __forceinline__ float2 unpack2(ull v) {
    float2 f;
    asm("mov.b64 {%0, %1}, %2;" : "=f"(f.x), "=f"(f.y) : "l"(v));
    return f;
}

// ---------------- edge dtype sniff + decode ----------------
__global__ void k_sniff(const long long* __restrict__ ei) {
    if (threadIdx.x == 0 && blockIdx.x == 0) {
        int ok = 1;
        for (int i = 0; i < 128; i++) {
            long long v = ei[i];
            if (v < 0 || v >= 2147483647LL) { ok = 0; break; }
        }
        g_is64 = ok;
    }
}

__global__ void k_decode(const void* __restrict__ eiv, int E, int n) {
    int e = blockIdx.x * blockDim.x + threadIdx.x;
    if (e >= E) return;
    int s, d;
    if (g_is64) {
        const long long* p = (const long long*)eiv;
        s = (int)__ldg(&p[e]);
        d = (int)__ldg(&p[(size_t)E + e]);
    } else {
        const int* p = (const int*)eiv;
        s = __ldg(&p[e]);
        d = __ldg(&p[(size_t)E + e]);
    }
    s = min(max(s, 0), n - 1);
    d = min(max(d, 0), n - 1);
    g_src[e] = s;
    g_dst[e] = d;
}

// ---------------- CSR build ----------------
__global__ void k_zero(int n) {
    int i = blockIdx.x * blockDim.x + threadIdx.x;
    if (i < n) { g_deg[i] = 0; g_cur[i] = 0; }
}

__global__ void k_hist(int E) {
    int e = blockIdx.x * blockDim.x + threadIdx.x;
    if (e < E) atomicAdd(&g_deg[g_dst[e]], 1);
}

__global__ void k_scan1(int n) {
    __shared__ int sh[1024];
    int t = threadIdx.x;
    int g = blockIdx.x * 1024 + t;
    int v = (g < n) ? g_deg[g] : 0;
    sh[t] = v;
    __syncthreads();
    for (int d = 1; d < 1024; d <<= 1) {
        int x = (t >= d) ? sh[t - d] : 0;
        __syncthreads();
        sh[t] += x;
        __syncthreads();
    }
    if (g < n) g_off[g] = sh[t] - v;       // exclusive within block
    if (t == 1023) g_bsum[blockIdx.x] = sh[1023];
}

__global__ void k_scan2(int nb) {
    __shared__ int sh[128];
    int t = threadIdx.x;
    int v = (t < nb) ? g_bsum[t] : 0;
    sh[t] = v;
    __syncthreads();
    for (int d = 1; d < 128; d <<= 1) {
        int x = (t >= d) ? sh[t - d] : 0;
        __syncthreads();
        sh[t] += x;
        __syncthreads();
    }
    if (t < nb) g_bsum[t] = sh[t] - v;     // exclusive
}

__global__ void k_scan3(int n, int E) {
    int g = blockIdx.x * 1024 + threadIdx.x;
    if (g < n)       g_off[g] += g_bsum[blockIdx.x];
    else if (g == n) g_off[n]  = E;
}

__global__ void k_fill(int E) {
    int e = blockIdx.x * blockDim.x + threadIdx.x;
    if (e >= E) return;
    int dst = g_dst[e];
    int p = atomicAdd(&g_cur[dst], 1);
    g_adj[g_off[dst] + p] = g_src[e];
}

// ---------------- weight / BN precompute ----------------
__global__ void k_precompute(const float* __restrict__ W1, const float* __restrict__ b1,
                             const float* __restrict__ W2, const float* __restrict__ b2,
                             const float* __restrict__ Wg1, const float* __restrict__ bg1,
                             const float* __restrict__ gamma, const float* __restrict__ beta,
                             const float* __restrict__ rmean, const float* __restrict__ rvar) {
    int b = blockIdx.x, j = threadIdx.x;   // j in [0,128)
    if (b < F1) {
        float acc = 0.f;
        #pragma unroll 8
        for (int i = 0; i < H; i++) acc = fmaf(W1[b * H + i], Wg1[i * H + j], acc);
        g_Wc[b * H + j] = FW * acc;
    } else if (b < KTOT) {
        int r = b - F1;
        float acc = 0.f;
        #pragma unroll 8
        for (int i = 0; i < H; i++) acc = fmaf(W2[r * H + i], Wg1[i * H + j], acc);
        g_Wc[b * H + j] = SW * acc;
    } else if (b == KTOT) {
        float acc = 0.f;
        for (int i = 0; i < H; i++) acc = fmaf(FW * b1[i] + SW * b2[i], Wg1[i * H + j], acc);
        g_bz[j] = acc;
    } else {
        float sc = gamma[j] * rsqrtf(rvar[j] + BN_EPS);
        g_scale[j] = sc;
        g_shift[j] = (bg1[j] - rmean[j]) * sc + beta[j];
    }
}

// ---------------- GEMM1: z = [x1|x2] @ Wc + bz   ([N,640]x[640,128]) ----------------
// Inner product via packed fma.rn.f32x2: 32 FFMA2 per k-step per thread.
__global__ __launch_bounds__(256) void k_gemm1(const float* __restrict__ x1,
                                               const float* __restrict__ x2, int n) {
    __shared__ float As[16][128];
    __shared__ float Bs[16][128];
    int tid = threadIdx.x;
    int m0 = blockIdx.x * 128;
    int tx = tid & 15, ty = tid >> 4;
    int tn = tx * 8, tm = ty * 8;
    ull acc2[8][4] = {};

    for (int k0 = 0; k0 < KTOT; k0 += 16) {
        const float* xa;
        int stride, kbase;
        if (k0 < F1) { xa = x1; stride = F1; kbase = k0; }
        else         { xa = x2; stride = F3; kbase = k0 - F1; }
        #pragma unroll
        for (int i = 0; i < 2; i++) {
            int f = tid + i * 256;            // 0..511
            int row = f >> 2;                 // 0..127
            int kq = (f & 3) * 4;             // 0,4,8,12
            int grow = m0 + row;
            float4 v = make_float4(0.f, 0.f, 0.f, 0.f);
            if (grow < n) v = *(const float4*)(xa + (size_t)grow * stride + kbase + kq);
            As[kq + 0][row] = v.x; As[kq + 1][row] = v.y;
            As[kq + 2][row] = v.z; As[kq + 3][row] = v.w;
        }
        #pragma unroll
        for (int i = 0; i < 2; i++) {
            int f = tid + i * 256;
            int row = f >> 5;                 // 0..15
            int cq = (f & 31) * 4;
            *(float4*)&Bs[row][cq] = *(const float4*)(g_Wc + (size_t)(k0 + row) * H + cq);
        }
        __syncthreads();
        #pragma unroll
        for (int k = 0; k < 16; k++) {
            float4 a0 = *(float4*)&As[k][tm];
            float4 a1 = *(float4*)&As[k][tm + 4];
            ulonglong2 bp0 = *(ulonglong2*)&Bs[k][tn];
            ulonglong2 bp1 = *(ulonglong2*)&Bs[k][tn + 4];
            ull b2v[4] = {bp0.x, bp0.y, bp1.x, bp1.y};
            float a[8] = {a0.x, a0.y, a0.z, a0.w, a1.x, a1.y, a1.z, a1.w};
            #pragma unroll
            for (int i = 0; i < 8; i++) {
                ull aa = pack2(a[i]);
                #pragma unroll
                for (int j = 0; j < 4; j++)
                    ffma2(acc2[i][j], aa, b2v[j]);
            }
        }
        __syncthreads();
    }
    #pragma unroll
    for (int i = 0; i < 8; i++) {
        int grow = m0 + tm + i;
        if (grow < n) {
            #pragma unroll
            for (int j = 0; j < 2; j++) {
                float2 p0 = unpack2(acc2[i][j * 2 + 0]);
                float2 p1 = unpack2(acc2[i][j * 2 + 1]);
                float4 v;
                v.x = p0.x + g_bz[tn + j * 4 + 0];
                v.y = p0.y + g_bz[tn + j * 4 + 1];
                v.z = p1.x + g_bz[tn + j * 4 + 2];
                v.w = p1.y + g_bz[tn + j * 4 + 3];
                *(float4*)(g_z + (size_t)grow * H + tn + j * 4) = v;
            }
        }
    }
}

// ---------------- gather-reduce layer 1 (+ BN + ReLU) ----------------
__global__ __launch_bounds__(256) void k_agg128(int n) {
    int w = (blockIdx.x * blockDim.x + threadIdx.x) >> 5;
    int lane = threadIdx.x & 31;
    if (w >= n) return;
    float4 sc = *(const float4*)(g_scale + lane * 4);
    float4 sh = *(const float4*)(g_shift + lane * 4);
    int s = g_off[w], e = g_off[w + 1];
    float4 acc = make_float4(0.f, 0.f, 0.f, 0.f);
    for (int i = s; i < e; i++) {
        int src = g_adj[i];
        float4 v = *(const float4*)(g_z + (size_t)src * H + lane * 4);
        acc.x += v.x; acc.y += v.y; acc.z += v.z; acc.w += v.w;
    }
    float4 r;
    r.x = fmaxf(fmaf(acc.x, sc.x, sh.x), 0.f);
    r.y = fmaxf(fmaf(acc.y, sc.y, sh.y), 0.f);
    r.z = fmaxf(fmaf(acc.z, sc.z, sh.z), 0.f);
    r.w = fmaxf(fmaf(acc.w, sc.w, sh.w), 0.f);
    *(float4*)(g_agg + (size_t)w * H + lane * 4) = r;
}

// ---------------- GEMM2: z2 = agg @ Wg2   ([N,128]x[128,64]) ----------------
__global__ __launch_bounds__(256) void k_gemm2(const float* __restrict__ Wg2, int n) {
    __shared__ float As[16][128];
    __shared__ float Bs[16][64];
    int tid = threadIdx.x;
    int m0 = blockIdx.x * 128;
    int tx = tid & 15, ty = tid >> 4;
    int tn = tx * 4, tm = ty * 8;
    ull acc2[8][2] = {};

    for (int k0 = 0; k0 < H; k0 += 16) {
        #pragma unroll
        for (int i = 0; i < 2; i++) {
            int f = tid + i * 256;
            int row = f >> 2;
            int kq = (f & 3) * 4;
            int grow = m0 + row;
            float4 v = make_float4(0.f, 0.f, 0.f, 0.f);
            if (grow < n) v = *(const float4*)(g_agg + (size_t)grow * H + k0 + kq);
            As[kq + 0][row] = v.x; As[kq + 1][row] = v.y;
            As[kq + 2][row] = v.z; As[kq + 3][row] = v.w;
        }
        {
            int row = tid >> 4;           // 0..15
            int cq = (tid & 15) * 4;      // 0..60
            *(float4*)&Bs[row][cq] = *(const float4*)(Wg2 + (size_t)(k0 + row) * C + cq);
        }
        __syncthreads();
        #pragma unroll
        for (int k = 0; k < 16; k++) {
            float4 a0 = *(float4*)&As[k][tm];
            float4 a1 = *(float4*)&As[k][tm + 4];
            ulonglong2 bp = *(ulonglong2*)&Bs[k][tn];
            ull b2v[2] = {bp.x, bp.y};
            float a[8] = {a0.x, a0.y, a0.z, a0.w, a1.x, a1.y, a1.z, a1.w};
            #pragma unroll
            for (int i = 0; i < 8; i++) {
                ull aa = pack2(a[i]);
                ffma2(acc2[i][0], aa, b2v[0]);
                ffma2(acc2[i][1], aa, b2v[1]);
            }
        }
        __syncthreads();
    }
    #pragma unroll
    for (int i = 0; i < 8; i++) {
        int grow = m0 + tm + i;
        if (grow < n) {
            float2 p0 = unpack2(acc2[i][0]);
            float2 p1 = unpack2(acc2[i][1]);
            float4 v = make_float4(p0.x, p0.y, p1.x, p1.y);
            *(float4*)(g_z2 + (size_t)grow * C + tn) = v;
        }
    }
}

// ---------------- gather-reduce layer 2 (+ bg2) -> out ----------------
__global__ __launch_bounds__(256) void k_agg64(const float* __restrict__ bg2,
                                               float* __restrict__ out, int n) {
    int w = (blockIdx.x * blockDim.x + threadIdx.x) >> 5;
    int lane = threadIdx.x & 31;
    if (w >= n) return;
    int s = g_off[w], e = g_off[w + 1];
    float2 acc = *(const float2*)(bg2 + lane * 2);
    for (int i = s; i < e; i++) {
        int src = g_adj[i];
        float2 v = *(const float2*)(g_z2 + (size_t)src * C + lane * 2);
        acc.x += v.x; acc.y += v.y;
    }
    *(float2*)(out + (size_t)w * C + lane * 2) = acc;
}

// ---------------- launch ----------------
extern "C" void kernel_launch(void* const* d_in, const int* in_sizes, int n_in,
                              void* d_out, int out_size) {
    const float* x1   = (const float*)d_in[0];
    const float* x2   = (const float*)d_in[1];
    const void*  ei   = (const void*)d_in[2];
    const float* W1   = (const float*)d_in[3];
    const float* b1   = (const float*)d_in[4];
    const float* W2   = (const float*)d_in[5];
    const float* b2   = (const float*)d_in[6];
    const float* Wg1  = (const float*)d_in[7];
    const float* bg1  = (const float*)d_in[8];
    const float* Wg2  = (const float*)d_in[9];
    const float* bg2  = (const float*)d_in[10];
    const float* gamma = (const float*)d_in[11];
    const float* beta  = (const float*)d_in[12];
    const float* rmean = (const float*)d_in[13];
    const float* rvar  = (const float*)d_in[14];
    float* out = (float*)d_out;

    int N = in_sizes[0] / F1;
    int E = in_sizes[2] / 2;

    int scan_blocks = (N + 1023) / 1024;           // covers n
    int scan_blocks3 = (N + 1024) / 1024;          // covers n+1

    // edge decode (dtype-robust) + CSR build
    k_sniff<<<1, 32>>>((const long long*)ei);
    k_decode<<<(E + 255) / 256, 256>>>(ei, E, N);
    k_zero<<<(N + 255) / 256, 256>>>(N);
    k_hist<<<(E + 255) / 256, 256>>>(E);
    k_scan1<<<scan_blocks, 1024>>>(N);
    k_scan2<<<1, 128>>>(scan_blocks);
    k_scan3<<<scan_blocks3, 1024>>>(N, E);
    k_fill<<<(E + 255) / 256, 256>>>(E);

    // weight + BN precompute
    k_precompute<<<KTOT + 2, H>>>(W1, b1, W2, b2, Wg1, bg1, gamma, beta, rmean, rvar);

    int gemm_blocks = (N + 127) / 128;
    int agg_blocks = (N + 7) / 8;                  // 8 warps per 256-thread block

    k_gemm1<<<gemm_blocks, 256>>>(x1, x2, N);
    k_agg128<<<agg_blocks, 256>>>(N);
    k_gemm2<<<gemm_blocks, 256>>>(Wg2, N);
    k_agg64<<<agg_blocks, 256>>>(bg2, out, N);
}

// round 12
// speedup vs baseline: 2.1075x; 2.1075x over previous
#include <cuda_runtime.h>
#include <cstdint>

#define NMAX 100000
#define EMAX 1600000
#define F1 512
#define F3 128
#define H 128
#define C 64
#define KTOT (F1 + F3)   // 640
#define SW 0.2f
#define FW 0.8f
#define BN_EPS 1e-5f

#define BM 128
#define BN 128
#define BK 16
#define LDA 136   // 128 + 8 pad -> bank (8k+m)%32 conflict-free
#define LDB 136

// ---------------- device scratch (static, no allocations) ----------------
__device__ int   g_is64;
__device__ int   g_src[EMAX];
__device__ int   g_dst[EMAX];
__device__ int   g_deg[NMAX + 1];
__device__ int   g_off[NMAX + 1];
__device__ int   g_cur[NMAX];
__device__ int   g_bsum[128];
__device__ int   g_adj[EMAX];
__device__ float g_Wc[KTOT * H];      // fused [640,128] weight
__device__ float g_bz[H];
__device__ float g_scale[H];
__device__ float g_shift[H];
__device__ float g_z[(size_t)NMAX * H];     // 51.2 MB
__device__ float g_agg[(size_t)NMAX * H];   // 51.2 MB (post BN+ReLU)
__device__ float g_z2[(size_t)NMAX * C];    // 25.6 MB

// ---------------- tf32 helpers ----------------
__device__ __forceinline__ float tf32f(float x) {
    uint32_t u;
    asm("cvt.rna.tf32.f32 %0, %1;" : "=r"(u) : "f"(x));
    return __uint_as_float(u);
}

__device__ __forceinline__ void mma_tf32(float* d, const uint32_t* a, const uint32_t* b) {
    asm volatile(
        "mma.sync.aligned.m16n8k8.row.col.f32.tf32.tf32.f32 "
        "{%0,%1,%2,%3}, {%4,%5,%6,%7}, {%8,%9}, {%0,%1,%2,%3};"
        : "+f"(d[0]), "+f"(d[1]), "+f"(d[2]), "+f"(d[3])
        : "r"(a[0]), "r"(a[1]), "r"(a[2]), "r"(a[3]), "r"(b[0]), "r"(b[1]));
}

// ---------------- edge dtype sniff + decode ----------------
__global__ void k_sniff(const long long* __restrict__ ei) {
    if (threadIdx.x == 0 && blockIdx.x == 0) {
        int ok = 1;
        for (int i = 0; i < 128; i++) {
            long long v = ei[i];
            if (v < 0 || v >= 2147483647LL) { ok = 0; break; }
        }
        g_is64 = ok;
    }
}

__global__ void k_decode(const void* __restrict__ eiv, int E, int n) {
    int e = blockIdx.x * blockDim.x + threadIdx.x;
    if (e >= E) return;
    int s, d;
    if (g_is64) {
        const long long* p = (const long long*)eiv;
        s = (int)__ldg(&p[e]);
        d = (int)__ldg(&p[(size_t)E + e]);
    } else {
        const int* p = (const int*)eiv;
        s = __ldg(&p[e]);
        d = __ldg(&p[(size_t)E + e]);
    }
    s = min(max(s, 0), n - 1);
    d = min(max(d, 0), n - 1);
    g_src[e] = s;
    g_dst[e] = d;
}

// ---------------- CSR build ----------------
__global__ void k_zero(int n) {
    int i = blockIdx.x * blockDim.x + threadIdx.x;
    if (i < n) { g_deg[i] = 0; g_cur[i] = 0; }
}

__global__ void k_hist(int E) {
    int e = blockIdx.x * blockDim.x + threadIdx.x;
    if (e < E) atomicAdd(&g_deg[g_dst[e]], 1);
}

__global__ void k_scan1(int n) {
    __shared__ int sh[1024];
    int t = threadIdx.x;
    int g = blockIdx.x * 1024 + t;
    int v = (g < n) ? g_deg[g] : 0;
    sh[t] = v;
    __syncthreads();
    for (int d = 1; d < 1024; d <<= 1) {
        int x = (t >= d) ? sh[t - d] : 0;
        __syncthreads();
        sh[t] += x;
        __syncthreads();
    }
    if (g < n) g_off[g] = sh[t] - v;       // exclusive within block
    if (t == 1023) g_bsum[blockIdx.x] = sh[1023];
}

__global__ void k_scan2(int nb) {
    __shared__ int sh[128];
    int t = threadIdx.x;
    int v = (t < nb) ? g_bsum[t] : 0;
    sh[t] = v;
    __syncthreads();
    for (int d = 1; d < 128; d <<= 1) {
        int x = (t >= d) ? sh[t - d] : 0;
        __syncthreads();
        sh[t] += x;
        __syncthreads();
    }
    if (t < nb) g_bsum[t] = sh[t] - v;     // exclusive
}

__global__ void k_scan3(int n, int E) {
    int g = blockIdx.x * 1024 + threadIdx.x;
    if (g < n)       g_off[g] += g_bsum[blockIdx.x];
    else if (g == n) g_off[n]  = E;
}

__global__ void k_fill(int E) {
    int e = blockIdx.x * blockDim.x + threadIdx.x;
    if (e >= E) return;
    int dst = g_dst[e];
    int p = atomicAdd(&g_cur[dst], 1);
    g_adj[g_off[dst] + p] = g_src[e];
}

// ---------------- weight / BN precompute ----------------
__global__ void k_precompute(const float* __restrict__ W1, const float* __restrict__ b1,
                             const float* __restrict__ W2, const float* __restrict__ b2,
                             const float* __restrict__ Wg1, const float* __restrict__ bg1,
                             const float* __restrict__ gamma, const float* __restrict__ beta,
                             const float* __restrict__ rmean, const float* __restrict__ rvar) {
    int b = blockIdx.x, j = threadIdx.x;   // j in [0,128)
    if (b < F1) {
        float acc = 0.f;
        #pragma unroll 8
        for (int i = 0; i < H; i++) acc = fmaf(W1[b * H + i], Wg1[i * H + j], acc);
        g_Wc[b * H + j] = FW * acc;
    } else if (b < KTOT) {
        int r = b - F1;
        float acc = 0.f;
        #pragma unroll 8
        for (int i = 0; i < H; i++) acc = fmaf(W2[r * H + i], Wg1[i * H + j], acc);
        g_Wc[b * H + j] = SW * acc;
    } else if (b == KTOT) {
        float acc = 0.f;
        for (int i = 0; i < H; i++) acc = fmaf(FW * b1[i] + SW * b2[i], Wg1[i * H + j], acc);
        g_bz[j] = acc;
    } else {
        float sc = gamma[j] * rsqrtf(rvar[j] + BN_EPS);
        g_scale[j] = sc;
        g_shift[j] = (bg1[j] - rmean[j]) * sc + beta[j];
    }
}

// ---------------- GEMM1 (tf32 tensor cores): z = [x1|x2] @ Wc + bz ----------------
// CTA tile 128x128, 8 warps (4 in M x 2 in N), warp tile 32x64,
// mma.sync.m16n8k8 tf32, fp32 accumulate. Smem k-major, pad 8 -> conflict-free.
__global__ __launch_bounds__(256) void k_gemm1(const float* __restrict__ x1,
                                               const float* __restrict__ x2, int n) {
    __shared__ float As[BK][LDA];   // [k][m]
    __shared__ float Bs[BK][LDB];   // [k][n]
    int tid = threadIdx.x;
    int lane = tid & 31;
    int warp = tid >> 5;
    int m0 = blockIdx.x * BM;
    int m_base = (warp & 3) * 32;   // warp M offset
    int n_base = (warp >> 2) * 64;  // warp N offset
    int gr = lane >> 2;             // 0..7
    int gc = lane & 3;              // 0..3

    float d[2][8][4] = {};

    for (int k0 = 0; k0 < KTOT; k0 += BK) {
        const float* xa;
        int stride, kbase;
        if (k0 < F1) { xa = x1; stride = F1; kbase = k0; }
        else         { xa = x2; stride = F3; kbase = k0 - F1; }
        // A tile: load row-major x, transpose into As[k][m] with tf32 rounding
        #pragma unroll
        for (int i = 0; i < 2; i++) {
            int f = tid + i * 256;            // 0..511
            int row = f >> 2;                 // 0..127
            int kq = (f & 3) * 4;             // 0,4,8,12
            int grow = m0 + row;
            float4 v = make_float4(0.f, 0.f, 0.f, 0.f);
            if (grow < n) v = *(const float4*)(xa + (size_t)grow * stride + kbase + kq);
            As[kq + 0][row] = tf32f(v.x);
            As[kq + 1][row] = tf32f(v.y);
            As[kq + 2][row] = tf32f(v.z);
            As[kq + 3][row] = tf32f(v.w);
        }
        // B tile: g_Wc already k-major [k][n]
        #pragma unroll
        for (int i = 0; i < 2; i++) {
            int f = tid + i * 256;
            int row = f >> 5;                 // 0..15
            int cq = (f & 31) * 4;
            float4 v = *(const float4*)(g_Wc + (size_t)(k0 + row) * H + cq);
            v.x = tf32f(v.x); v.y = tf32f(v.y); v.z = tf32f(v.z); v.w = tf32f(v.w);
            *(float4*)&Bs[row][cq] = v;
        }
        __syncthreads();

        #pragma unroll
        for (int kk = 0; kk < BK; kk += 8) {
            uint32_t a[2][4];
            uint32_t b[8][2];
            #pragma unroll
            for (int mt = 0; mt < 2; mt++) {
                int r = m_base + mt * 16 + gr;
                int c = kk + gc;
                a[mt][0] = __float_as_uint(As[c][r]);
                a[mt][1] = __float_as_uint(As[c][r + 8]);
                a[mt][2] = __float_as_uint(As[c + 4][r]);
                a[mt][3] = __float_as_uint(As[c + 4][r + 8]);
            }
            #pragma unroll
            for (int nt = 0; nt < 8; nt++) {
                int nn = n_base + nt * 8 + gr;
                b[nt][0] = __float_as_uint(Bs[kk + gc][nn]);
                b[nt][1] = __float_as_uint(Bs[kk + gc + 4][nn]);
            }
            #pragma unroll
            for (int mt = 0; mt < 2; mt++)
                #pragma unroll
                for (int nt = 0; nt < 8; nt++)
                    mma_tf32(d[mt][nt], a[mt], b[nt]);
        }
        __syncthreads();
    }

    // epilogue: d[mt][nt] element (row,col): c0:(gr, gc*2) c1:(gr, gc*2+1) c2:(gr+8,..) c3
    int gc2 = gc * 2;
    #pragma unroll
    for (int mt = 0; mt < 2; mt++) {
        int r0 = m0 + m_base + mt * 16 + gr;
        int r1 = r0 + 8;
        #pragma unroll
        for (int nt = 0; nt < 8; nt++) {
            int col = n_base + nt * 8 + gc2;
            if (r0 < n) {
                float2 v;
                v.x = d[mt][nt][0] + g_bz[col];
                v.y = d[mt][nt][1] + g_bz[col + 1];
                *(float2*)(g_z + (size_t)r0 * H + col) = v;
            }
            if (r1 < n) {
                float2 v;
                v.x = d[mt][nt][2] + g_bz[col];
                v.y = d[mt][nt][3] + g_bz[col + 1];
                *(float2*)(g_z + (size_t)r1 * H + col) = v;
            }
        }
    }
}

// ---------------- gather-reduce layer 1 (+ BN + ReLU) ----------------
__global__ __launch_bounds__(256) void k_agg128(int n) {
    int w = (blockIdx.x * blockDim.x + threadIdx.x) >> 5;
    int lane = threadIdx.x & 31;
    if (w >= n) return;
    float4 sc = *(const float4*)(g_scale + lane * 4);
    float4 sh = *(const float4*)(g_shift + lane * 4);
    int s = g_off[w], e = g_off[w + 1];
    float4 acc = make_float4(0.f, 0.f, 0.f, 0.f);
    for (int i = s; i < e; i++) {
        int src = g_adj[i];
        float4 v = *(const float4*)(g_z + (size_t)src * H + lane * 4);
        acc.x += v.x; acc.y += v.y; acc.z += v.z; acc.w += v.w;
    }
    float4 r;
    r.x = fmaxf(fmaf(acc.x, sc.x, sh.x), 0.f);
    r.y = fmaxf(fmaf(acc.y, sc.y, sh.y), 0.f);
    r.z = fmaxf(fmaf(acc.z, sc.z, sh.z), 0.f);
    r.w = fmaxf(fmaf(acc.w, sc.w, sh.w), 0.f);
    *(float4*)(g_agg + (size_t)w * H + lane * 4) = r;
}

// ---------------- GEMM2: z2 = agg @ Wg2   ([N,128]x[128,64]) scalar fp32 ----------------
__global__ __launch_bounds__(256) void k_gemm2(const float* __restrict__ Wg2, int n) {
    __shared__ float As2[16][128];
    __shared__ float Bs2[16][64];
    int tid = threadIdx.x;
    int m0 = blockIdx.x * 128;
    int tx = tid & 15, ty = tid >> 4;
    int tn = tx * 4, tm = ty * 8;
    float acc[8][4] = {};

    for (int k0 = 0; k0 < H; k0 += 16) {
        #pragma unroll
        for (int i = 0; i < 2; i++) {
            int f = tid + i * 256;
            int row = f >> 2;
            int kq = (f & 3) * 4;
            int grow = m0 + row;
            float4 v = make_float4(0.f, 0.f, 0.f, 0.f);
            if (grow < n) v = *(const float4*)(g_agg + (size_t)grow * H + k0 + kq);
            As2[kq + 0][row] = v.x; As2[kq + 1][row] = v.y;
            As2[kq + 2][row] = v.z; As2[kq + 3][row] = v.w;
        }
        {
            int row = tid >> 4;           // 0..15
            int cq = (tid & 15) * 4;      // 0..60
            *(float4*)&Bs2[row][cq] = *(const float4*)(Wg2 + (size_t)(k0 + row) * C + cq);
        }
        __syncthreads();
        #pragma unroll
        for (int k = 0; k < 16; k++) {
            float4 a0 = *(float4*)&As2[k][tm];
            float4 a1 = *(float4*)&As2[k][tm + 4];
            float4 bv = *(float4*)&Bs2[k][tn];
            float a[8] = {a0.x, a0.y, a0.z, a0.w, a1.x, a1.y, a1.z, a1.w};
            float b[4] = {bv.x, bv.y, bv.z, bv.w};
            #pragma unroll
            for (int i = 0; i < 8; i++)
                #pragma unroll
                for (int j = 0; j < 4; j++)
                    acc[i][j] = fmaf(a[i], b[j], acc[i][j]);
        }
        __syncthreads();
    }
    #pragma unroll
    for (int i = 0; i < 8; i++) {
        int grow = m0 + tm + i;
        if (grow < n) {
            float4 v = make_float4(acc[i][0], acc[i][1], acc[i][2], acc[i][3]);
            *(float4*)(g_z2 + (size_t)grow * C + tn) = v;
        }
    }
}

// ---------------- gather-reduce layer 2 (+ bg2) -> out ----------------
__global__ __launch_bounds__(256) void k_agg64(const float* __restrict__ bg2,
                                               float* __restrict__ out, int n) {
    int w = (blockIdx.x * blockDim.x + threadIdx.x) >> 5;
    int lane = threadIdx.x & 31;
    if (w >= n) return;
    int s = g_off[w], e = g_off[w + 1];
    float2 acc = *(const float2*)(bg2 + lane * 2);
    for (int i = s; i < e; i++) {
        int src = g_adj[i];
        float2 v = *(const float2*)(g_z2 + (size_t)src * C + lane * 2);
        acc.x += v.x; acc.y += v.y;
    }
    *(float2*)(out + (size_t)w * C + lane * 2) = acc;
}

// ---------------- launch ----------------
extern "C" void kernel_launch(void* const* d_in, const int* in_sizes, int n_in,
                              void* d_out, int out_size) {
    const float* x1   = (const float*)d_in[0];
    const float* x2   = (const float*)d_in[1];
    const void*  ei   = (const void*)d_in[2];
    const float* W1   = (const float*)d_in[3];
    const float* b1   = (const float*)d_in[4];
    const float* W2   = (const float*)d_in[5];
    const float* b2   = (const float*)d_in[6];
    const float* Wg1  = (const float*)d_in[7];
    const float* bg1  = (const float*)d_in[8];
    const float* Wg2  = (const float*)d_in[9];
    const float* bg2  = (const float*)d_in[10];
    const float* gamma = (const float*)d_in[11];
    const float* beta  = (const float*)d_in[12];
    const float* rmean = (const float*)d_in[13];
    const float* rvar  = (const float*)d_in[14];
    float* out = (float*)d_out;

    int N = in_sizes[0] / F1;
    int E = in_sizes[2] / 2;

    int scan_blocks = (N + 1023) / 1024;           // covers n
    int scan_blocks3 = (N + 1024) / 1024;          // covers n+1

    // edge decode (dtype-robust) + CSR build
    k_sniff<<<1, 32>>>((const long long*)ei);
    k_decode<<<(E + 255) / 256, 256>>>(ei, E, N);
    k_zero<<<(N + 255) / 256, 256>>>(N);
    k_hist<<<(E + 255) / 256, 256>>>(E);
    k_scan1<<<scan_blocks, 1024>>>(N);
    k_scan2<<<1, 128>>>(scan_blocks);
    k_scan3<<<scan_blocks3, 1024>>>(N, E);
    k_fill<<<(E + 255) / 256, 256>>>(E);

    // weight + BN precompute
    k_precompute<<<KTOT + 2, H>>>(W1, b1, W2, b2, Wg1, bg1, gamma, beta, rmean, rvar);

    int gemm_blocks = (N + 127) / 128;
    int agg_blocks = (N + 7) / 8;                  // 8 warps per 256-thread block

    k_gemm1<<<gemm_blocks, 256>>>(x1, x2, N);
    k_agg128<<<agg_blocks, 256>>>(N);
    k_gemm2<<<gemm_blocks, 256>>>(Wg2, N);
    k_agg64<<<agg_blocks, 256>>>(bg2, out, N);
}

// round 17
// speedup vs baseline: 2.9477x; 1.3987x over previous
#include <cuda_runtime.h>
#include <cstdint>

#define NMAX 100000
#define EMAX 1600000
#define F1 512
#define F3 128
#define H 128
#define C 64
#define KTOT (F1 + F3)   // 640
#define SW 0.2f
#define FW 0.8f
#define BN_EPS 1e-5f

#define BM 128
#define BK 16
#define LDA2 20   // 16 + 4 pad: A row-major fragment banks (20*gr+gc)%32 distinct
#define LDB 136   // 128 + 8 pad: B fragment banks (8*gc+gr)%32 distinct
#define LDB2 72   // 64 + 8 pad

// ---------------- device scratch (static, no allocations) ----------------
__device__ int   g_is64;
__device__ int   g_src[EMAX];
__device__ int   g_dst[EMAX];
__device__ int   g_deg[NMAX + 1];
__device__ int   g_off[NMAX + 1];
__device__ int   g_cur[NMAX];
__device__ int   g_bsum[128];
__device__ int   g_adj[EMAX];
__device__ float g_Wc[KTOT * H];      // fused [640,128] weight
__device__ float g_bz[H];
__device__ float g_scale[H];
__device__ float g_shift[H];
__device__ float g_z[(size_t)NMAX * H];
__device__ float g_agg[(size_t)NMAX * H];
__device__ float g_z2[(size_t)NMAX * C];

// ---------------- helpers ----------------
__device__ __forceinline__ uint32_t smem_u32(const void* p) {
    return (uint32_t)__cvta_generic_to_shared(p);
}
__device__ __forceinline__ void cpa16(uint32_t dst, const void* src, int sz) {
    asm volatile("cp.async.ca.shared.global [%0], [%1], 16, %2;"
                 :: "r"(dst), "l"(src), "r"(sz));
}
__device__ __forceinline__ void cpa_commit() {
    asm volatile("cp.async.commit_group;");
}
template <int N_>
__device__ __forceinline__ void cpa_wait() {
    asm volatile("cp.async.wait_group %0;" :: "n"(N_));
}
__device__ __forceinline__ uint32_t tf32u(float x) {
    uint32_t u;
    asm("cvt.rna.tf32.f32 %0, %1;" : "=r"(u) : "f"(x));
    return u;
}
__device__ __forceinline__ void mma_tf32(float* d, const uint32_t* a, const uint32_t* b) {
    asm volatile(
        "mma.sync.aligned.m16n8k8.row.col.f32.tf32.tf32.f32 "
        "{%0,%1,%2,%3}, {%4,%5,%6,%7}, {%8,%9}, {%0,%1,%2,%3};"
        : "+f"(d[0]), "+f"(d[1]), "+f"(d[2]), "+f"(d[3])
        : "r"(a[0]), "r"(a[1]), "r"(a[2]), "r"(a[3]), "r"(b[0]), "r"(b[1]));
}

// ---------------- edge dtype sniff + decode ----------------
__global__ void k_sniff(const long long* __restrict__ ei) {
    if (threadIdx.x == 0 && blockIdx.x == 0) {
        int ok = 1;
        for (int i = 0; i < 128; i++) {
            long long v = ei[i];
            if (v < 0 || v >= 2147483647LL) { ok = 0; break; }
        }
        g_is64 = ok;
    }
}

__global__ void k_decode(const void* __restrict__ eiv, int E, int n) {
    int e = blockIdx.x * blockDim.x + threadIdx.x;
    if (e >= E) return;
    int s, d;
    if (g_is64) {
        const long long* p = (const long long*)eiv;
        s = (int)__ldg(&p[e]);
        d = (int)__ldg(&p[(size_t)E + e]);
    } else {
        const int* p = (const int*)eiv;
        s = __ldg(&p[e]);
        d = __ldg(&p[(size_t)E + e]);
    }
    s = min(max(s, 0), n - 1);
    d = min(max(d, 0), n - 1);
    g_src[e] = s;
    g_dst[e] = d;
}

// ---------------- CSR build ----------------
__global__ void k_zero(int n) {
    int i = blockIdx.x * blockDim.x + threadIdx.x;
    if (i < n) { g_deg[i] = 0; g_cur[i] = 0; }
}

__global__ void k_hist(int E) {
    int e = blockIdx.x * blockDim.x + threadIdx.x;
    if (e < E) atomicAdd(&g_deg[g_dst[e]], 1);
}

__global__ void k_scan1(int n) {
    __shared__ int sh[1024];
    int t = threadIdx.x;
    int g = blockIdx.x * 1024 + t;
    int v = (g < n) ? g_deg[g] : 0;
    sh[t] = v;
    __syncthreads();
    for (int d = 1; d < 1024; d <<= 1) {
        int x = (t >= d) ? sh[t - d] : 0;
        __syncthreads();
        sh[t] += x;
        __syncthreads();
    }
    if (g < n) g_off[g] = sh[t] - v;
    if (t == 1023) g_bsum[blockIdx.x] = sh[1023];
}

__global__ void k_scan2(int nb) {
    __shared__ int sh[128];
    int t = threadIdx.x;
    int v = (t < nb) ? g_bsum[t] : 0;
    sh[t] = v;
    __syncthreads();
    for (int d = 1; d < 128; d <<= 1) {
        int x = (t >= d) ? sh[t - d] : 0;
        __syncthreads();
        sh[t] += x;
        __syncthreads();
    }
    if (t < nb) g_bsum[t] = sh[t] - v;
}

__global__ void k_scan3(int n, int E) {
    int g = blockIdx.x * 1024 + threadIdx.x;
    if (g < n)       g_off[g] += g_bsum[blockIdx.x];
    else if (g == n) g_off[n]  = E;
}

__global__ void k_fill(int E) {
    int e = blockIdx.x * blockDim.x + threadIdx.x;
    if (e >= E) return;
    int dst = g_dst[e];
    int p = atomicAdd(&g_cur[dst], 1);
    g_adj[g_off[dst] + p] = g_src[e];
}

// ---------------- weight / BN precompute ----------------
__global__ void k_precompute(const float* __restrict__ W1, const float* __restrict__ b1,
                             const float* __restrict__ W2, const float* __restrict__ b2,
                             const float* __restrict__ Wg1, const float* __restrict__ bg1,
                             const float* __restrict__ gamma, const float* __restrict__ beta,
                             const float* __restrict__ rmean, const float* __restrict__ rvar) {
    int b = blockIdx.x, j = threadIdx.x;
    if (b < F1) {
        float acc = 0.f;
        #pragma unroll 8
        for (int i = 0; i < H; i++) acc = fmaf(W1[b * H + i], Wg1[i * H + j], acc);
        g_Wc[b * H + j] = FW * acc;
    } else if (b < KTOT) {
        int r = b - F1;
        float acc = 0.f;
        #pragma unroll 8
        for (int i = 0; i < H; i++) acc = fmaf(W2[r * H + i], Wg1[i * H + j], acc);
        g_Wc[b * H + j] = SW * acc;
    } else if (b == KTOT) {
        float acc = 0.f;
        for (int i = 0; i < H; i++) acc = fmaf(FW * b1[i] + SW * b2[i], Wg1[i * H + j], acc);
        g_bz[j] = acc;
    } else {
        float sc = gamma[j] * rsqrtf(rvar[j] + BN_EPS);
        g_scale[j] = sc;
        g_shift[j] = (bg1[j] - rmean[j]) * sc + beta[j];
    }
}

// ---------------- GEMM1 (tf32, cp.async double-buffered) ----------------
// z = [x1|x2] @ Wc + bz. CTA 128x128, warp tile 32x64.
// A row-major smem [m][k] pad->20; tf32 cvt on fragment load.
__global__ __launch_bounds__(256) void k_gemm1(const float* __restrict__ x1,
                                               const float* __restrict__ x2, int n) {
    __shared__ float As[2][BM][LDA2];
    __shared__ float Bs[2][BK][LDB];
    int tid = threadIdx.x;
    int lane = tid & 31;
    int warp = tid >> 5;
    int m0 = blockIdx.x * BM;
    int m_base = (warp & 3) * 32;
    int n_base = (warp >> 2) * 64;
    int gr = lane >> 2;
    int gc = lane & 3;

    const int NT = KTOT / BK;   // 40 tiles

    // per-thread load coords (2 segs A, 2 segs B)
    int fa0 = tid, fa1 = tid + 256;
    int ra0 = fa0 >> 2, sa0 = (fa0 & 3) * 4;
    int ra1 = fa1 >> 2, sa1 = (fa1 & 3) * 4;
    int rb0 = fa0 >> 5, cb0 = (fa0 & 31) * 4;
    int rb1 = fa1 >> 5, cb1 = (fa1 & 31) * 4;

    int gr0 = m0 + ra0, gr1 = m0 + ra1;
    int sz0 = (gr0 < n) ? 16 : 0, sz1 = (gr1 < n) ? 16 : 0;
    int gc0 = min(gr0, n - 1), gc1 = min(gr1, n - 1);

    auto load_tile = [&](int st, int k0) {
        const float* xa; int stride, kbase;
        if (k0 < F1) { xa = x1; stride = F1; kbase = k0; }
        else         { xa = x2; stride = F3; kbase = k0 - F1; }
        cpa16(smem_u32(&As[st][ra0][sa0]), xa + (size_t)gc0 * stride + kbase + sa0, sz0);
        cpa16(smem_u32(&As[st][ra1][sa1]), xa + (size_t)gc1 * stride + kbase + sa1, sz1);
        cpa16(smem_u32(&Bs[st][rb0][cb0]), g_Wc + (size_t)(k0 + rb0) * H + cb0, 16);
        cpa16(smem_u32(&Bs[st][rb1][cb1]), g_Wc + (size_t)(k0 + rb1) * H + cb1, 16);
        cpa_commit();
    };

    float d[2][8][4] = {};

    load_tile(0, 0);
    for (int it = 0; it < NT; it++) {
        int st = it & 1;
        if (it + 1 < NT) {
            load_tile(st ^ 1, (it + 1) * BK);
            cpa_wait<1>();
        } else {
            cpa_wait<0>();
        }
        __syncthreads();

        #pragma unroll
        for (int kk = 0; kk < BK; kk += 8) {
            uint32_t a[2][4];
            uint32_t b[8][2];
            #pragma unroll
            for (int mt = 0; mt < 2; mt++) {
                int r = m_base + mt * 16 + gr;
                int c = kk + gc;
                a[mt][0] = tf32u(As[st][r][c]);
                a[mt][1] = tf32u(As[st][r + 8][c]);
                a[mt][2] = tf32u(As[st][r][c + 4]);
                a[mt][3] = tf32u(As[st][r + 8][c + 4]);
            }
            #pragma unroll
            for (int nt = 0; nt < 8; nt++) {
                int nn = n_base + nt * 8 + gr;
                b[nt][0] = tf32u(Bs[st][kk + gc][nn]);
                b[nt][1] = tf32u(Bs[st][kk + gc + 4][nn]);
            }
            #pragma unroll
            for (int mt = 0; mt < 2; mt++)
                #pragma unroll
                for (int nt = 0; nt < 8; nt++)
                    mma_tf32(d[mt][nt], a[mt], b[nt]);
        }
        __syncthreads();
    }

    int gc2 = gc * 2;
    #pragma unroll
    for (int mt = 0; mt < 2; mt++) {
        int r0 = m0 + m_base + mt * 16 + gr;
        int r1 = r0 + 8;
        #pragma unroll
        for (int nt = 0; nt < 8; nt++) {
            int col = n_base + nt * 8 + gc2;
            if (r0 < n) {
                float2 v;
                v.x = d[mt][nt][0] + g_bz[col];
                v.y = d[mt][nt][1] + g_bz[col + 1];
                *(float2*)(g_z + (size_t)r0 * H + col) = v;
            }
            if (r1 < n) {
                float2 v;
                v.x = d[mt][nt][2] + g_bz[col];
                v.y = d[mt][nt][3] + g_bz[col + 1];
                *(float2*)(g_z + (size_t)r1 * H + col) = v;
            }
        }
    }
}

// ---------------- gather-reduce layer 1 (+ BN + ReLU) ----------------
__global__ __launch_bounds__(256) void k_agg128(int n) {
    int w = (blockIdx.x * blockDim.x + threadIdx.x) >> 5;
    int lane = threadIdx.x & 31;
    if (w >= n) return;
    float4 sc = *(const float4*)(g_scale + lane * 4);
    float4 sh = *(const float4*)(g_shift + lane * 4);
    int s = g_off[w], e = g_off[w + 1];
    float4 acc = make_float4(0.f, 0.f, 0.f, 0.f);
    for (int i = s; i < e; i++) {
        int src = g_adj[i];
        float4 v = *(const float4*)(g_z + (size_t)src * H + lane * 4);
        acc.x += v.x; acc.y += v.y; acc.z += v.z; acc.w += v.w;
    }
    float4 r;
    r.x = fmaxf(fmaf(acc.x, sc.x, sh.x), 0.f);
    r.y = fmaxf(fmaf(acc.y, sc.y, sh.y), 0.f);
    r.z = fmaxf(fmaf(acc.z, sc.z, sh.z), 0.f);
    r.w = fmaxf(fmaf(acc.w, sc.w, sh.w), 0.f);
    *(float4*)(g_agg + (size_t)w * H + lane * 4) = r;
}

// ---------------- GEMM2 (tf32, cp.async double-buffered) ----------------
// z2 = agg @ Wg2. CTA 128x64, warp tile 32x32 (4 warps M x 2 warps N).
__global__ __launch_bounds__(256) void k_gemm2(const float* __restrict__ Wg2, int n) {
    __shared__ float As[2][BM][LDA2];
    __shared__ float Bs[2][BK][LDB2];
    int tid = threadIdx.x;
    int lane = tid & 31;
    int warp = tid >> 5;
    int m0 = blockIdx.x * BM;
    int m_base = (warp & 3) * 32;
    int n_base = (warp >> 2) * 32;
    int gr = lane >> 2;
    int gc = lane & 3;

    const int NT = H / BK;   // 8 tiles

    int fa0 = tid, fa1 = tid + 256;
    int ra0 = fa0 >> 2, sa0 = (fa0 & 3) * 4;
    int ra1 = fa1 >> 2, sa1 = (fa1 & 3) * 4;
    int rb = tid >> 4, cb = (tid & 15) * 4;   // B: 16x64 = 256 segs

    int gr0 = m0 + ra0, gr1 = m0 + ra1;
    int sz0 = (gr0 < n) ? 16 : 0, sz1 = (gr1 < n) ? 16 : 0;
    int gc0 = min(gr0, n - 1), gc1 = min(gr1, n - 1);

    auto load_tile = [&](int st, int k0) {
        cpa16(smem_u32(&As[st][ra0][sa0]), g_agg + (size_t)gc0 * H + k0 + sa0, sz0);
        cpa16(smem_u32(&As[st][ra1][sa1]), g_agg + (size_t)gc1 * H + k0 + sa1, sz1);
        cpa16(smem_u32(&Bs[st][rb][cb]), Wg2 + (size_t)(k0 + rb) * C + cb, 16);
        cpa_commit();
    };

    float d[2][4][4] = {};

    load_tile(0, 0);
    for (int it = 0; it < NT; it++) {
        int st = it & 1;
        if (it + 1 < NT) {
            load_tile(st ^ 1, (it + 1) * BK);
            cpa_wait<1>();
        } else {
            cpa_wait<0>();
        }
        __syncthreads();

        #pragma unroll
        for (int kk = 0; kk < BK; kk += 8) {
            uint32_t a[2][4];
            uint32_t b[4][2];
            #pragma unroll
            for (int mt = 0; mt < 2; mt++) {
                int r = m_base + mt * 16 + gr;
                int c = kk + gc;
                a[mt][0] = tf32u(As[st][r][c]);
                a[mt][1] = tf32u(As[st][r + 8][c]);
                a[mt][2] = tf32u(As[st][r][c + 4]);
                a[mt][3] = tf32u(As[st][r + 8][c + 4]);
            }
            #pragma unroll
            for (int nt = 0; nt < 4; nt++) {
                int nn = n_base + nt * 8 + gr;
                b[nt][0] = tf32u(Bs[st][kk + gc][nn]);
                b[nt][1] = tf32u(Bs[st][kk + gc + 4][nn]);
            }
            #pragma unroll
            for (int mt = 0; mt < 2; mt++)
                #pragma unroll
                for (int nt = 0; nt < 4; nt++)
                    mma_tf32(d[mt][nt], a[mt], b[nt]);
        }
        __syncthreads();
    }

    int gc2 = gc * 2;
    #pragma unroll
    for (int mt = 0; mt < 2; mt++) {
        int r0 = m0 + m_base + mt * 16 + gr;
        int r1 = r0 + 8;
        #pragma unroll
        for (int nt = 0; nt < 4; nt++) {
            int col = n_base + nt * 8 + gc2;
            if (r0 < n) {
                float2 v = make_float2(d[mt][nt][0], d[mt][nt][1]);
                *(float2*)(g_z2 + (size_t)r0 * C + col) = v;
            }
            if (r1 < n) {
                float2 v = make_float2(d[mt][nt][2], d[mt][nt][3]);
                *(float2*)(g_z2 + (size_t)r1 * C + col) = v;
            }
        }
    }
}

// ---------------- gather-reduce layer 2 (+ bg2) -> out ----------------
__global__ __launch_bounds__(256) void k_agg64(const float* __restrict__ bg2,
                                               float* __restrict__ out, int n) {
    int w = (blockIdx.x * blockDim.x + threadIdx.x) >> 5;
    int lane = threadIdx.x & 31;
    if (w >= n) return;
    int s = g_off[w], e = g_off[w + 1];
    float2 acc = *(const float2*)(bg2 + lane * 2);
    for (int i = s; i < e; i++) {
        int src = g_adj[i];
        float2 v = *(const float2*)(g_z2 + (size_t)src * C + lane * 2);
        acc.x += v.x; acc.y += v.y;
    }
    *(float2*)(out + (size_t)w * C + lane * 2) = acc;
}

// ---------------- launch ----------------
extern "C" void kernel_launch(void* const* d_in, const int* in_sizes, int n_in,
                              void* d_out, int out_size) {
    const float* x1   = (const float*)d_in[0];
    const float* x2   = (const float*)d_in[1];
    const void*  ei   = (const void*)d_in[2];
    const float* W1   = (const float*)d_in[3];
    const float* b1   = (const float*)d_in[4];
    const float* W2   = (const float*)d_in[5];
    const float* b2   = (const float*)d_in[6];
    const float* Wg1  = (const float*)d_in[7];
    const float* bg1  = (const float*)d_in[8];
    const float* Wg2  = (const float*)d_in[9];
    const float* bg2  = (const float*)d_in[10];
    const float* gamma = (const float*)d_in[11];
    const float* beta  = (const float*)d_in[12];
    const float* rmean = (const float*)d_in[13];
    const float* rvar  = (const float*)d_in[14];
    float* out = (float*)d_out;

    int N = in_sizes[0] / F1;
    int E = in_sizes[2] / 2;

    int scan_blocks = (N + 1023) / 1024;
    int scan_blocks3 = (N + 1024) / 1024;

    k_sniff<<<1, 32>>>((const long long*)ei);
    k_decode<<<(E + 255) / 256, 256>>>(ei, E, N);
    k_zero<<<(N + 255) / 256, 256>>>(N);
    k_hist<<<(E + 255) / 256, 256>>>(E);
    k_scan1<<<scan_blocks, 1024>>>(N);
    k_scan2<<<1, 128>>>(scan_blocks);
    k_scan3<<<scan_blocks3, 1024>>>(N, E);
    k_fill<<<(E + 255) / 256, 256>>>(E);

    k_precompute<<<KTOT + 2, H>>>(W1, b1, W2, b2, Wg1, bg1, gamma, beta, rmean, rvar);

    int gemm_blocks = (N + 127) / 128;
    int agg_blocks = (N + 7) / 8;

    k_gemm1<<<gemm_blocks, 256>>>(x1, x2, N);
    k_agg128<<<agg_blocks, 256>>>(N);
    k_gemm2<<<gemm_blocks, 256>>>(Wg2, N);
    k_agg64<<<agg_blocks, 256>>>(bg2, out, N);
}